// round 3
// baseline (speedup 1.0000x reference)
#include <cuda_runtime.h>
#include <cuda_bf16.h>

// YOLOv3 loss, sm_103a — single fused kernel, R3.
// R3 changes: division-free IoU argmax (cross-multiplied comparison), and
// 2 anchors per thread for ILP + shared-load amortization in the hot loop.

#define NUM_CLASSES 80
#define MAXB 64
#define MAXM 64
#define APT 2            // anchors per thread
#define TPB 256

__device__ float        g_cls_sum[MAXB];   // zero-initialized at module load
__device__ float        g_reg_sum[MAXB];
__device__ float        g_npos[MAXB];
__device__ unsigned int g_done;

__device__ __forceinline__ float sigmoidf_fast(float x) {
    return 1.0f / (1.0f + __expf(-x));
}

__global__ void __launch_bounds__(TPB)
yolo_loss_fused(const float* __restrict__ pred,
                const float* __restrict__ ann,
                const float* __restrict__ anchors,
                float* __restrict__ out,
                int A, int M, int B) {
    __shared__ float4 s_corners[MAXM];               // x1,y1,x2,y2
    __shared__ float  s_area[MAXM];
    __shared__ float  s_cx[MAXM], s_cy[MAXM], s_w[MAXM], s_h[MAXM], s_cl[MAXM];
    __shared__ int    s_cnt;
    __shared__ int    s_last;

    const int b   = blockIdx.y;
    const int tid = threadIdx.x;

    // ---- warp 0: load + compact valid boxes (M <= 32), order-preserving ----
    if (tid < 32) {
        bool  valid = false;
        float x = 0.f, y = 0.f, w = 0.f, h = 0.f, cl = -1.f;
        if (tid < M) {
            const float* bm = ann + ((size_t)b * M + tid) * 5;
            x = bm[0]; y = bm[1]; w = bm[2]; h = bm[3]; cl = bm[4];
            valid = (cl != -1.0f);
        }
        unsigned mask = __ballot_sync(0xffffffffu, valid);
        if (valid) {
            int slot = __popc(mask & ((1u << tid) - 1u));
            s_corners[slot] = make_float4(x, y, x + w, y + h);
            s_area[slot] = w * h;
            s_cx[slot] = x + 0.5f * w;
            s_cy[slot] = y + 0.5f * h;
            s_w[slot]  = w;
            s_h[slot]  = h;
            s_cl[slot] = cl;
        }
        if (tid == 0) s_cnt = __popc(mask);
    }
    __syncthreads();

    const int cnt  = s_cnt;
    const int base = blockIdx.x * (TPB * APT) + tid;

    float ax[APT], ay[APT], aw_[APT], ah_[APT];
    float x1[APT], y1[APT], x2[APT], y2[APT], areaA[APT];
    bool  act[APT];

    #pragma unroll
    for (int j = 0; j < APT; j++) {
        int a = base + j * TPB;
        act[j] = (a < A);
        float4 an = act[j] ? __ldg((const float4*)anchors + a)
                           : make_float4(0.f, 0.f, 1.f, 1.f);
        ax[j] = an.x; ay[j] = an.y; aw_[j] = an.z; ah_[j] = an.w;
        x1[j] = an.x - 0.5f * an.z;  y1[j] = an.y - 0.5f * an.w;
        x2[j] = an.x + 0.5f * an.z;  y2[j] = an.y + 0.5f * an.w;
        areaA[j] = an.z * an.w;
    }

    // best tracked as (inter, union) pair; compare a/b > c/d via a*d > c*b.
    // init (-1, 1): first valid box always wins (inter*1 > -1*union), and the
    // strict '>' keeps the FIRST max afterwards — matches jnp.argmax.
    float bI[APT], bU[APT];
    int   bi[APT];
    #pragma unroll
    for (int j = 0; j < APT; j++) { bI[j] = -1.f; bU[j] = 1.f; bi[j] = 0; }

    #pragma unroll 4
    for (int m = 0; m < cnt; m++) {
        const float4 c  = s_corners[m];
        const float  am = s_area[m];
        #pragma unroll
        for (int j = 0; j < APT; j++) {
            float iw = fminf(x2[j], c.z) - fmaxf(x1[j], c.x);
            float ih = fminf(y2[j], c.w) - fmaxf(y1[j], c.y);
            iw = fmaxf(iw, 0.f);
            ih = fmaxf(ih, 0.f);
            float inter = iw * ih;
            float uni   = areaA[j] + am - inter;
            if (inter * bU[j] > bI[j] * uni) {
                bI[j] = inter; bU[j] = uni; bi[j] = m;
            }
        }
    }

    float clsc = 0.f, regc = 0.f, posc = 0.f;

    #pragma unroll
    for (int j = 0; j < APT; j++) {
        // best_iou >= 0.5  ⟺  2*best_inter >= best_union  (union > 0 always)
        if (act[j] && (2.0f * bI[j] >= bU[j])) {
            int k = bi[j];
            int a = base + j * TPB;
            posc += 1.f;
            const float* row = pred + ((size_t)b * A + a) * (NUM_CLASSES + 5);

            // regression: sum of squared errors (both /denom deferred)
            float r0 = row[0], r1 = row[1], r2 = row[2], r3 = row[3], r4 = row[4];
            float stx = sigmoidf_fast(s_cx[k] - ax[j]);
            float sty = sigmoidf_fast(s_cy[k] - ay[j]);
            float tw  = __logf(fmaxf(s_w[k], 1.f) / aw_[j]);
            float th  = __logf(fmaxf(s_h[k], 1.f) / ah_[j]);
            float d0 = sigmoidf_fast(r0) - stx;
            float d1 = sigmoidf_fast(r1) - sty;
            float d2 = r2 - tw;
            float d3 = r3 - th;
            float d4 = r4 - 1.0f;
            regc += d0*d0 + d1*d1 + d2*d2 + d3*d3 + d4*d4;

            // one-hot BCE collapsed: -( log p_t - log(1-p_t) + sum_c log(1-p_c) )
            float acc = 0.f;
            #pragma unroll 8
            for (int c = 0; c < NUM_CLASSES; c++)
                acc += __logf(1.0f - row[5 + c]);
            int t = (int)s_cl[k];
            float pt = row[5 + t];
            clsc += -(__logf(pt) - __logf(1.0f - pt) + acc);
        }
    }

    // warp reduce, one conditional atomic triple per warp
    const unsigned full = 0xffffffffu;
    #pragma unroll
    for (int off = 16; off > 0; off >>= 1) {
        clsc += __shfl_down_sync(full, clsc, off);
        regc += __shfl_down_sync(full, regc, off);
        posc += __shfl_down_sync(full, posc, off);
    }
    if ((tid & 31) == 0 && posc > 0.f) {
        atomicAdd(&g_cls_sum[b], clsc);
        atomicAdd(&g_reg_sum[b], regc);
        atomicAdd(&g_npos[b],    posc);
    }

    // ---- last-block finalize ----
    __syncthreads();
    if (tid == 0) {
        __threadfence();
        unsigned total = gridDim.x * gridDim.y;
        unsigned old = atomicAdd(&g_done, 1u);
        s_last = (old == total - 1u);
    }
    __syncthreads();

    if (s_last && tid < 32) {
        __threadfence();
        float cl = 0.f, rg = 0.f;
        if (tid < B) {
            float n = g_npos[tid];
            float denom = fmaxf(n, 1.f);
            cl = g_cls_sum[tid] / denom;
            rg = (n > 0.f) ? g_reg_sum[tid] / (denom * denom) : 0.f;
            g_cls_sum[tid] = 0.f;
            g_reg_sum[tid] = 0.f;
            g_npos[tid]    = 0.f;
        }
        #pragma unroll
        for (int off = 16; off > 0; off >>= 1) {
            cl += __shfl_down_sync(full, cl, off);
            rg += __shfl_down_sync(full, rg, off);
        }
        if (tid == 0) {
            out[0] = cl / (float)B;
            out[1] = rg / (float)B;
            g_done = 0u;
        }
    }
}

extern "C" void kernel_launch(void* const* d_in, const int* in_sizes, int n_in,
                              void* d_out, int out_size) {
    const float* pred    = (const float*)d_in[0];  // (B, A, 5+C) f32
    const float* ann     = (const float*)d_in[1];  // (B, M, 5) f32
    const float* anchors = (const float*)d_in[2];  // (A, 4) f32
    float* out = (float*)d_out;

    const int A = in_sizes[2] / 4;
    const int B = in_sizes[0] / (A * (NUM_CLASSES + 5));
    const int M = in_sizes[1] / (B * 5);

    dim3 grid((A + TPB * APT - 1) / (TPB * APT), B);
    yolo_loss_fused<<<grid, TPB>>>(pred, ann, anchors, out, A, M, B);
}